// round 2
// baseline (speedup 1.0000x reference)
#include <cuda_runtime.h>
#include <math.h>

// ParallelRNN: B=4096, H=256, L=32, I=64 (fp32 everywhere)
// Grid: 2048 blocks = (l fastest, 64 batch tiles), 256 threads/block.
// Each block: full GRU+MLP chain for (l, 64 batch rows).
// GEMM: thread micro-tile 4 rows x 16 cols, packed f32x2 accumulators.

#define DEVI __device__ __forceinline__

static constexpr int Bb   = 4096;
static constexpr int Hh   = 256;
static constexpr int Ll   = 32;
static constexpr int Ii   = 64;
static constexpr int BT   = 64;          // batch rows per block
static constexpr int HS   = 258;         // bufA/bufB row stride (floats)
static constexpr int XS   = 68;          // xm row stride
static constexpr int WK   = 16;          // weight tile K rows
static constexpr int WS   = 260;         // weight tile row stride (floats)
static constexpr int BHL  = Bb * Hh * Ll;    // 33554432
static constexpr int BL   = Bb * Ll;         // 131072

// smem layout (floats)
static constexpr int OFF_A   = 0;
static constexpr int OFF_B   = OFF_A + BT * HS;          // 16512
static constexpr int OFF_W   = OFF_B + BT * HS;          // 33024
static constexpr int OFF_XM  = OFF_W + 3 * WK * WS;      // 45504
static constexpr int OFF_WMU = OFF_XM + BT * XS;         // 49856
static constexpr int SMEM_FLOATS = OFF_WMU + 256;        // 50112
static constexpr int SMEM_BYTES  = SMEM_FLOATS * 4;      // 200448

DEVI unsigned int s2u(const void* p) {
    unsigned int a;
    asm("{ .reg .u64 t; cvta.to.shared.u64 t, %1; cvt.u32.u64 %0, t; }"
        : "=r"(a) : "l"(p));
    return a;
}

DEVI void ffma2(unsigned long long& d, unsigned long long a, unsigned long long b) {
    asm("fma.rn.f32x2 %0, %1, %2, %0;" : "+l"(d) : "l"(a), "l"(b));
}

DEVI unsigned long long packf2(float x, float y) {
    unsigned long long v;
    asm("mov.b64 %0, {%1, %2};" : "=l"(v) : "f"(x), "f"(y));
    return v;
}

DEVI float2 unpackf2(unsigned long long v) {
    float2 f;
    asm("mov.b64 {%0, %1}, %2;" : "=f"(f.x), "=f"(f.y) : "l"(v));
    return f;
}

DEVI float sigm(float v) { return 1.0f / (1.0f + expf(-v)); }

// copy one WK x 256 weight tile (kt-th) into wbuf slot `buf` via cp.async
DEVI void issue_tile(const float* __restrict__ gW, int kt, int buf,
                     unsigned int wsm_u32, int tid) {
    const float* gsrc = gW + kt * WK * Hh;
    unsigned int sbase = wsm_u32 + (unsigned int)buf * (WK * WS * 4);
#pragma unroll
    for (int q = 0; q < 4; ++q) {                 // WK*64 f4 / 256 thr = 4
        int idx = tid + 256 * q;
        int row = idx >> 6;
        int c4  = idx & 63;
        unsigned int sa = sbase + (unsigned int)(row * WS + c4 * 4) * 4u;
        const float* ga = gsrc + row * Hh + c4 * 4;
        asm volatile("cp.async.cg.shared.global [%0], [%1], 16;"
                     :: "r"(sa), "l"(ga));
    }
}

// acc[r][p] += in_s[BT x KTOT] @ gW[KTOT x 256] for this thread's micro-tile
template <int KTOT, int INSTRIDE>
DEVI void gemm_pass(unsigned long long acc[4][8], const float* __restrict__ gW,
                    const float* in_s, const float* wsm, unsigned int wsm_u32,
                    int tid, int tr4, int tc) {
    constexpr int T = KTOT / WK;
    issue_tile(gW, 0, 0, wsm_u32, tid);
    asm volatile("cp.async.commit_group;");
    for (int t = 0; t < T; ++t) {
        if (t + 1 < T) issue_tile(gW, t + 1, (t + 1) % 3, wsm_u32, tid);
        asm volatile("cp.async.commit_group;");
        asm volatile("cp.async.wait_group 1;");
        __syncthreads();
        const float* wb   = wsm + (t % 3) * (WK * WS);
        const float* arow = in_s + tr4 * INSTRIDE + t * WK;
#pragma unroll
        for (int k = 0; k < WK; ++k) {
            unsigned long long hp[4];
#pragma unroll
            for (int r = 0; r < 4; ++r) {
                float hv = arow[r * INSTRIDE + k];
                hp[r] = packf2(hv, hv);
            }
            const float* wr = wb + k * WS + tc * 4;
#pragma unroll
            for (int j = 0; j < 4; ++j) {
                float4 w4 = *reinterpret_cast<const float4*>(wr + 64 * j);
                unsigned long long w01 = packf2(w4.x, w4.y);
                unsigned long long w23 = packf2(w4.z, w4.w);
#pragma unroll
                for (int r = 0; r < 4; ++r) {
                    ffma2(acc[r][2 * j],     hp[r], w01);
                    ffma2(acc[r][2 * j + 1], hp[r], w23);
                }
            }
        }
    }
    __syncthreads();   // protect wbuf slot 0 before the next pass's prologue
}

__global__ void __launch_bounds__(256, 1)
prnn_kernel(const float* __restrict__ hidden, const float* __restrict__ x,
            const float* __restrict__ mask,
            const float* __restrict__ Wir, const float* __restrict__ bir,
            const float* __restrict__ Wiz, const float* __restrict__ biz,
            const float* __restrict__ Win, const float* __restrict__ bin_,
            const float* __restrict__ Whr, const float* __restrict__ Whz,
            const float* __restrict__ Whn, const float* __restrict__ bhn,
            const float* __restrict__ W1,  const float* __restrict__ b1,
            const float* __restrict__ W2,  const float* __restrict__ b2,
            const float* __restrict__ Wmu, const float* __restrict__ bmu,
            const float* __restrict__ log_var, float* __restrict__ out) {
    extern __shared__ float smem[];
    float* bufA  = smem + OFF_A;
    float* bufB  = smem + OFF_B;
    float* wsm   = smem + OFF_W;
    float* xm    = smem + OFF_XM;
    float* wmu_s = smem + OFF_WMU;
    const unsigned int wsm_u32 = s2u(wsm);

    const int tid = threadIdx.x;
    const int tc  = tid & 15;
    const int tr4 = (tid >> 4) * 4;
    const int bx  = blockIdx.x;
    const int l   = bx & 31;
    const int b0  = (bx >> 5) * BT;

    // ---- load h tile: bufA[row][col] = hidden[b0+row, col, l] ----
#pragma unroll 8
    for (int q = 0; q < BT; ++q) {
        bufA[q * HS + tid] = hidden[(b0 + q) * (Hh * Ll) + tid * Ll + l];
    }
    // ---- masked input tile: xm[row][i] = x[b0+row, i] * mask[i, l] ----
#pragma unroll
    for (int q = 0; q < 16; ++q) {
        int idx = tid + 256 * q;
        int row = idx >> 6, i = idx & 63;
        xm[row * XS + i] = x[(b0 + row) * Ii + i] * mask[i * Ll + l];
    }
    wmu_s[tid] = Wmu[l * Hh + tid];
    // (no explicit sync needed: first gemm_pass syncs before any compute)

    unsigned long long acc[4][8];
    unsigned long long rn[4][8];

    // ================= pass A: r = sigmoid(hh_r + xi_r + bir) =================
#pragma unroll
    for (int r = 0; r < 4; ++r)
#pragma unroll
        for (int p = 0; p < 8; ++p) acc[r][p] = 0ull;
    gemm_pass<256, HS>(acc, Whr + l * Hh * Hh, bufA, wsm, wsm_u32, tid, tr4, tc);
    gemm_pass<64,  XS>(acc, Wir + l * Ii * Hh, xm,   wsm, wsm_u32, tid, tr4, tc);
    {
        const float* bb = bir + l * Hh;
#pragma unroll
        for (int r = 0; r < 4; ++r)
#pragma unroll
            for (int p = 0; p < 8; ++p) {
                int cp = tc * 4 + (p >> 1) * 64 + (p & 1) * 2;
                float2 a = unpackf2(acc[r][p]);
                rn[r][p] = packf2(sigm(a.x + bb[cp]), sigm(a.y + bb[cp + 1]));
            }
    }

    // ============ pass B: n = tanh(xi_n + bin + r*(hh_n + bhn)) ============
#pragma unroll
    for (int r = 0; r < 4; ++r)
#pragma unroll
        for (int p = 0; p < 8; ++p) acc[r][p] = 0ull;
    gemm_pass<256, HS>(acc, Whn + l * Hh * Hh, bufA, wsm, wsm_u32, tid, tr4, tc);
    {
        const float* bb = bhn + l * Hh;
#pragma unroll
        for (int r = 0; r < 4; ++r)
#pragma unroll
            for (int p = 0; p < 8; ++p) {
                int cp = tc * 4 + (p >> 1) * 64 + (p & 1) * 2;
                float2 a  = unpackf2(acc[r][p]);
                float2 rr = unpackf2(rn[r][p]);
                acc[r][p] = packf2(rr.x * (a.x + bb[cp]),
                                   rr.y * (a.y + bb[cp + 1]));
            }
    }
    gemm_pass<64, XS>(acc, Win + l * Ii * Hh, xm, wsm, wsm_u32, tid, tr4, tc);
    {
        const float* bb = bin_ + l * Hh;
#pragma unroll
        for (int r = 0; r < 4; ++r)
#pragma unroll
            for (int p = 0; p < 8; ++p) {
                int cp = tc * 4 + (p >> 1) * 64 + (p & 1) * 2;
                float2 a = unpackf2(acc[r][p]);
                rn[r][p] = packf2(tanhf(a.x + bb[cp]), tanhf(a.y + bb[cp + 1]));
            }
    }

    // ====== pass C: z = sigmoid(hh_z + xi_z + biz); hnew = n + z*(h-n) ======
#pragma unroll
    for (int r = 0; r < 4; ++r)
#pragma unroll
        for (int p = 0; p < 8; ++p) acc[r][p] = 0ull;
    gemm_pass<256, HS>(acc, Whz + l * Hh * Hh, bufA, wsm, wsm_u32, tid, tr4, tc);
    gemm_pass<64,  XS>(acc, Wiz + l * Ii * Hh, xm,   wsm, wsm_u32, tid, tr4, tc);
    {
        const float* bb = biz + l * Hh;
#pragma unroll
        for (int r = 0; r < 4; ++r)
#pragma unroll
            for (int p = 0; p < 8; ++p) {
                int cp = tc * 4 + (p >> 1) * 64 + (p & 1) * 2;
                float2 a  = unpackf2(acc[r][p]);
                float2 nn = unpackf2(rn[r][p]);
                float zx = sigm(a.x + bb[cp]);
                float zy = sigm(a.y + bb[cp + 1]);
                float hx = bufA[(tr4 + r) * HS + cp];
                float hy = bufA[(tr4 + r) * HS + cp + 1];
                float2 hv;
                hv.x = nn.x + zx * (hx - nn.x);
                hv.y = nn.y + zy * (hy - nn.y);
                *reinterpret_cast<float2*>(&bufB[(tr4 + r) * HS + cp]) = hv;
            }
    }

    // ================= pass D: h1 = relu(hnew @ W1 + b1) =================
#pragma unroll
    for (int r = 0; r < 4; ++r)
#pragma unroll
        for (int p = 0; p < 8; ++p) acc[r][p] = 0ull;
    gemm_pass<256, HS>(acc, W1 + l * Hh * Hh, bufB, wsm, wsm_u32, tid, tr4, tc);
    {
        const float* bb = b1 + l * Hh;
#pragma unroll
        for (int r = 0; r < 4; ++r)
#pragma unroll
            for (int p = 0; p < 8; ++p) {
                int cp = tc * 4 + (p >> 1) * 64 + (p & 1) * 2;
                float2 a = unpackf2(acc[r][p]);
                float2 hv;
                hv.x = fmaxf(a.x + bb[cp], 0.0f);
                hv.y = fmaxf(a.y + bb[cp + 1], 0.0f);
                *reinterpret_cast<float2*>(&bufA[(tr4 + r) * HS + cp]) = hv;
            }
    }

    // ======== pass E: h2 = relu(h1 @ W2 + b2); store + mu reduction ========
#pragma unroll
    for (int r = 0; r < 4; ++r)
#pragma unroll
        for (int p = 0; p < 8; ++p) acc[r][p] = 0ull;
    gemm_pass<256, HS>(acc, W2 + l * Hh * Hh, bufA, wsm, wsm_u32, tid, tr4, tc);
    float mup[4] = {0.f, 0.f, 0.f, 0.f};
    {
        const float* bb = b2 + l * Hh;
#pragma unroll
        for (int r = 0; r < 4; ++r) {
            int brow = b0 + tr4 + r;
#pragma unroll
            for (int p = 0; p < 8; ++p) {
                int cp = tc * 4 + (p >> 1) * 64 + (p & 1) * 2;
                float2 a = unpackf2(acc[r][p]);
                float h2x = fmaxf(a.x + bb[cp], 0.0f);
                float h2y = fmaxf(a.y + bb[cp + 1], 0.0f);
                // transposed store: out[b, hcol, l]
                out[brow * (Hh * Ll) + cp * Ll + l]       = h2x;
                out[brow * (Hh * Ll) + (cp + 1) * Ll + l] = h2y;
                mup[r] += h2x * wmu_s[cp] + h2y * wmu_s[cp + 1];
            }
        }
    }
    // reduce mu over the 16 column-threads (lanes 0..15 / 16..31 per warp)
#pragma unroll
    for (int r = 0; r < 4; ++r) {
#pragma unroll
        for (int o = 8; o >= 1; o >>= 1)
            mup[r] += __shfl_down_sync(0xffffffffu, mup[r], o, 16);
    }
    if (tc == 0) {
        float lvv = fmaxf(log_var[l], -3.0f);
        float bm  = bmu[l];
#pragma unroll
        for (int r = 0; r < 4; ++r) {
            int brow = b0 + tr4 + r;
            out[BHL + brow * Ll + l]      = mup[r] + bm;
            out[BHL + BL + brow * Ll + l] = lvv;
        }
    }
}

extern "C" void kernel_launch(void* const* d_in, const int* in_sizes, int n_in,
                              void* d_out, int out_size) {
    const float* hidden  = (const float*)d_in[0];
    const float* x       = (const float*)d_in[1];
    const float* mask    = (const float*)d_in[2];
    const float* Wir     = (const float*)d_in[3];
    const float* bir     = (const float*)d_in[4];
    const float* Wiz     = (const float*)d_in[5];
    const float* biz     = (const float*)d_in[6];
    const float* Win     = (const float*)d_in[7];
    const float* bin_    = (const float*)d_in[8];
    const float* Whr     = (const float*)d_in[9];
    const float* Whz     = (const float*)d_in[10];
    const float* Whn     = (const float*)d_in[11];
    const float* bhn     = (const float*)d_in[12];
    const float* W1      = (const float*)d_in[13];
    const float* b1      = (const float*)d_in[14];
    const float* W2      = (const float*)d_in[15];
    const float* b2      = (const float*)d_in[16];
    const float* Wmu     = (const float*)d_in[17];
    const float* bmu     = (const float*)d_in[18];
    const float* log_var = (const float*)d_in[19];
    float* out = (float*)d_out;

    cudaFuncSetAttribute(prnn_kernel,
                         cudaFuncAttributeMaxDynamicSharedMemorySize, SMEM_BYTES);

    dim3 grid(Ll * (Bb / BT));   // 2048 blocks, l fastest -> L2 weight reuse
    dim3 block(256);
    prnn_kernel<<<grid, block, SMEM_BYTES>>>(
        hidden, x, mask, Wir, bir, Wiz, biz, Win, bin_,
        Whr, Whz, Whn, bhn, W1, b1, W2, b2, Wmu, bmu, log_var, out);
}

// round 3
// speedup vs baseline: 1.2380x; 1.2380x over previous
#include <cuda_runtime.h>
#include <math.h>

// ParallelRNN: B=4096, H=256, L=32, I=64 (fp32 everywhere)
// R2: 128-thread CTAs, BT=32, ~100KB smem -> 2 CTAs/SM so independent CTAs
// cover each other's barrier/cp.async stalls. Micro-tile stays 4x16 (f32x2).

#define DEVI __device__ __forceinline__

static constexpr int Bb   = 4096;
static constexpr int Hh   = 256;
static constexpr int Ll   = 32;
static constexpr int Ii   = 64;
static constexpr int BT   = 32;          // batch rows per block
static constexpr int NT   = 128;         // threads per block
static constexpr int HS   = 258;         // bufA/bufB row stride (floats)
static constexpr int XS   = 68;          // xm row stride
static constexpr int WK   = 8;           // weight tile K rows
static constexpr int WS   = 256;         // weight tile row stride (floats, no pad needed)
static constexpr int BHL  = Bb * Hh * Ll;    // 33554432
static constexpr int BL   = Bb * Ll;         // 131072

// smem layout (floats)
static constexpr int OFF_A   = 0;
static constexpr int OFF_B   = OFF_A + BT * HS;          // 8256
static constexpr int OFF_W   = OFF_B + BT * HS;          // 16512
static constexpr int OFF_XM  = OFF_W + 3 * WK * WS;      // 22656
static constexpr int OFF_WMU = OFF_XM + BT * XS;         // 24832
static constexpr int SMEM_FLOATS = OFF_WMU + 256;        // 25088
static constexpr int SMEM_BYTES  = SMEM_FLOATS * 4;      // 100352  -> 2 CTAs/SM

DEVI unsigned int s2u(const void* p) {
    unsigned int a;
    asm("{ .reg .u64 t; cvta.to.shared.u64 t, %1; cvt.u32.u64 %0, t; }"
        : "=r"(a) : "l"(p));
    return a;
}

DEVI void ffma2(unsigned long long& d, unsigned long long a, unsigned long long b) {
    asm("fma.rn.f32x2 %0, %1, %2, %0;" : "+l"(d) : "l"(a), "l"(b));
}

DEVI unsigned long long packf2(float x, float y) {
    unsigned long long v;
    asm("mov.b64 %0, {%1, %2};" : "=l"(v) : "f"(x), "f"(y));
    return v;
}

DEVI float2 unpackf2(unsigned long long v) {
    float2 f;
    asm("mov.b64 {%0, %1}, %2;" : "=f"(f.x), "=f"(f.y) : "l"(v));
    return f;
}

DEVI float sigm(float v) { return __fdividef(1.0f, 1.0f + __expf(-v)); }

// copy one WK x 256 weight tile (kt-th) into wbuf slot `buf` via cp.async
DEVI void issue_tile(const float* __restrict__ gW, int kt, int buf,
                     unsigned int wsm_u32, int tid) {
    const float* gsrc = gW + kt * WK * Hh;
    unsigned int sbase = wsm_u32 + (unsigned int)buf * (WK * WS * 4);
#pragma unroll
    for (int q = 0; q < 4; ++q) {                 // WK*64 f4 / 128 thr = 4
        int idx = tid + NT * q;
        int row = idx >> 6;
        int c4  = idx & 63;
        unsigned int sa = sbase + (unsigned int)(row * WS + c4 * 4) * 4u;
        const float* ga = gsrc + row * Hh + c4 * 4;
        asm volatile("cp.async.cg.shared.global [%0], [%1], 16;"
                     :: "r"(sa), "l"(ga));
    }
}

// acc[r][p] += in_s[BT x KTOT] @ gW[KTOT x 256] for this thread's micro-tile
template <int KTOT, int INSTRIDE>
DEVI void gemm_pass(unsigned long long acc[4][8], const float* __restrict__ gW,
                    const float* in_s, const float* wsm, unsigned int wsm_u32,
                    int tid, int tr4, int tc) {
    constexpr int T = KTOT / WK;
    issue_tile(gW, 0, 0, wsm_u32, tid);
    asm volatile("cp.async.commit_group;");
    for (int t = 0; t < T; ++t) {
        if (t + 1 < T) issue_tile(gW, t + 1, (t + 1) % 3, wsm_u32, tid);
        asm volatile("cp.async.commit_group;");
        asm volatile("cp.async.wait_group 1;");
        __syncthreads();
        const float* wb   = wsm + (t % 3) * (WK * WS);
        const float* arow = in_s + tr4 * INSTRIDE + t * WK;
#pragma unroll
        for (int k = 0; k < WK; ++k) {
            unsigned long long hp[4];
#pragma unroll
            for (int r = 0; r < 4; ++r) {
                float hv = arow[r * INSTRIDE + k];
                hp[r] = packf2(hv, hv);
            }
            const float* wr = wb + k * WS + tc * 4;
#pragma unroll
            for (int j = 0; j < 4; ++j) {
                float4 w4 = *reinterpret_cast<const float4*>(wr + 64 * j);
                unsigned long long w01 = packf2(w4.x, w4.y);
                unsigned long long w23 = packf2(w4.z, w4.w);
#pragma unroll
                for (int r = 0; r < 4; ++r) {
                    ffma2(acc[r][2 * j],     hp[r], w01);
                    ffma2(acc[r][2 * j + 1], hp[r], w23);
                }
            }
        }
    }
    __syncthreads();   // protect wbuf slot 0 before the next pass's prologue
}

__global__ void __launch_bounds__(NT, 2)
prnn_kernel(const float* __restrict__ hidden, const float* __restrict__ x,
            const float* __restrict__ mask,
            const float* __restrict__ Wir, const float* __restrict__ bir,
            const float* __restrict__ Wiz, const float* __restrict__ biz,
            const float* __restrict__ Win, const float* __restrict__ bin_,
            const float* __restrict__ Whr, const float* __restrict__ Whz,
            const float* __restrict__ Whn, const float* __restrict__ bhn,
            const float* __restrict__ W1,  const float* __restrict__ b1,
            const float* __restrict__ W2,  const float* __restrict__ b2,
            const float* __restrict__ Wmu, const float* __restrict__ bmu,
            const float* __restrict__ log_var, float* __restrict__ out) {
    extern __shared__ float smem[];
    float* bufA  = smem + OFF_A;
    float* bufB  = smem + OFF_B;
    float* wsm   = smem + OFF_W;
    float* xm    = smem + OFF_XM;
    float* wmu_s = smem + OFF_WMU;
    const unsigned int wsm_u32 = s2u(wsm);

    const int tid = threadIdx.x;
    const int tc  = tid & 15;
    const int tr4 = (tid >> 4) * 4;          // 8 row groups -> rows 0..31
    const int bx  = blockIdx.x;
    const int l   = bx & 31;
    const int b0  = (bx >> 5) * BT;

    // ---- load h tile: bufA[row][col] = hidden[b0+row, col, l] ----
#pragma unroll 4
    for (int q = 0; q < BT; ++q) {
        const float* hb = hidden + (size_t)(b0 + q) * (Hh * Ll) + l;
        bufA[q * HS + tid]      = hb[tid * Ll];
        bufA[q * HS + tid + NT] = hb[(tid + NT) * Ll];
    }
    // ---- masked input tile: xm[row][i] = x[b0+row, i] * mask[i, l] ----
#pragma unroll
    for (int q = 0; q < 16; ++q) {
        int idx = tid + NT * q;
        int row = idx >> 6, i = idx & 63;
        xm[row * XS + i] = x[(b0 + row) * Ii + i] * mask[i * Ll + l];
    }
    wmu_s[tid]      = Wmu[l * Hh + tid];
    wmu_s[tid + NT] = Wmu[l * Hh + tid + NT];
    // (no explicit sync needed: first gemm_pass syncs before any compute)

    unsigned long long acc[4][8];
    unsigned long long rn[4][8];

    // ================= pass A: r = sigmoid(hh_r + xi_r + bir) =================
#pragma unroll
    for (int r = 0; r < 4; ++r)
#pragma unroll
        for (int p = 0; p < 8; ++p) acc[r][p] = 0ull;
    gemm_pass<256, HS>(acc, Whr + l * Hh * Hh, bufA, wsm, wsm_u32, tid, tr4, tc);
    gemm_pass<64,  XS>(acc, Wir + l * Ii * Hh, xm,   wsm, wsm_u32, tid, tr4, tc);
    {
        const float* bb = bir + l * Hh;
#pragma unroll
        for (int r = 0; r < 4; ++r)
#pragma unroll
            for (int p = 0; p < 8; ++p) {
                int cp = tc * 4 + (p >> 1) * 64 + (p & 1) * 2;
                float2 a = unpackf2(acc[r][p]);
                rn[r][p] = packf2(sigm(a.x + bb[cp]), sigm(a.y + bb[cp + 1]));
            }
    }

    // ============ pass B: n = tanh(xi_n + bin + r*(hh_n + bhn)) ============
#pragma unroll
    for (int r = 0; r < 4; ++r)
#pragma unroll
        for (int p = 0; p < 8; ++p) acc[r][p] = 0ull;
    gemm_pass<256, HS>(acc, Whn + l * Hh * Hh, bufA, wsm, wsm_u32, tid, tr4, tc);
    {
        const float* bb = bhn + l * Hh;
#pragma unroll
        for (int r = 0; r < 4; ++r)
#pragma unroll
            for (int p = 0; p < 8; ++p) {
                int cp = tc * 4 + (p >> 1) * 64 + (p & 1) * 2;
                float2 a  = unpackf2(acc[r][p]);
                float2 rr = unpackf2(rn[r][p]);
                acc[r][p] = packf2(rr.x * (a.x + bb[cp]),
                                   rr.y * (a.y + bb[cp + 1]));
            }
    }
    gemm_pass<64, XS>(acc, Win + l * Ii * Hh, xm, wsm, wsm_u32, tid, tr4, tc);
    {
        const float* bb = bin_ + l * Hh;
#pragma unroll
        for (int r = 0; r < 4; ++r)
#pragma unroll
            for (int p = 0; p < 8; ++p) {
                int cp = tc * 4 + (p >> 1) * 64 + (p & 1) * 2;
                float2 a = unpackf2(acc[r][p]);
                rn[r][p] = packf2(tanhf(a.x + bb[cp]), tanhf(a.y + bb[cp + 1]));
            }
    }

    // ====== pass C: z = sigmoid(hh_z + xi_z + biz); hnew = n + z*(h-n) ======
#pragma unroll
    for (int r = 0; r < 4; ++r)
#pragma unroll
        for (int p = 0; p < 8; ++p) acc[r][p] = 0ull;
    gemm_pass<256, HS>(acc, Whz + l * Hh * Hh, bufA, wsm, wsm_u32, tid, tr4, tc);
    gemm_pass<64,  XS>(acc, Wiz + l * Ii * Hh, xm,   wsm, wsm_u32, tid, tr4, tc);
    {
        const float* bb = biz + l * Hh;
#pragma unroll
        for (int r = 0; r < 4; ++r)
#pragma unroll
            for (int p = 0; p < 8; ++p) {
                int cp = tc * 4 + (p >> 1) * 64 + (p & 1) * 2;
                float2 a  = unpackf2(acc[r][p]);
                float2 nn = unpackf2(rn[r][p]);
                float zx = sigm(a.x + bb[cp]);
                float zy = sigm(a.y + bb[cp + 1]);
                float hx = bufA[(tr4 + r) * HS + cp];
                float hy = bufA[(tr4 + r) * HS + cp + 1];
                float2 hv;
                hv.x = nn.x + zx * (hx - nn.x);
                hv.y = nn.y + zy * (hy - nn.y);
                *reinterpret_cast<float2*>(&bufB[(tr4 + r) * HS + cp]) = hv;
            }
    }

    // ================= pass D: h1 = relu(hnew @ W1 + b1) =================
#pragma unroll
    for (int r = 0; r < 4; ++r)
#pragma unroll
        for (int p = 0; p < 8; ++p) acc[r][p] = 0ull;
    gemm_pass<256, HS>(acc, W1 + l * Hh * Hh, bufB, wsm, wsm_u32, tid, tr4, tc);
    {
        const float* bb = b1 + l * Hh;
#pragma unroll
        for (int r = 0; r < 4; ++r)
#pragma unroll
            for (int p = 0; p < 8; ++p) {
                int cp = tc * 4 + (p >> 1) * 64 + (p & 1) * 2;
                float2 a = unpackf2(acc[r][p]);
                float2 hv;
                hv.x = fmaxf(a.x + bb[cp], 0.0f);
                hv.y = fmaxf(a.y + bb[cp + 1], 0.0f);
                *reinterpret_cast<float2*>(&bufA[(tr4 + r) * HS + cp]) = hv;
            }
    }

    // ======== pass E: h2 = relu(h1 @ W2 + b2); store + mu reduction ========
#pragma unroll
    for (int r = 0; r < 4; ++r)
#pragma unroll
        for (int p = 0; p < 8; ++p) acc[r][p] = 0ull;
    gemm_pass<256, HS>(acc, W2 + l * Hh * Hh, bufA, wsm, wsm_u32, tid, tr4, tc);
    float mup[4] = {0.f, 0.f, 0.f, 0.f};
    {
        const float* bb = b2 + l * Hh;
#pragma unroll
        for (int r = 0; r < 4; ++r) {
            int brow = b0 + tr4 + r;
#pragma unroll
            for (int p = 0; p < 8; ++p) {
                int cp = tc * 4 + (p >> 1) * 64 + (p & 1) * 2;
                float2 a = unpackf2(acc[r][p]);
                float h2x = fmaxf(a.x + bb[cp], 0.0f);
                float h2y = fmaxf(a.y + bb[cp + 1], 0.0f);
                // transposed store: out[b, hcol, l]
                out[(size_t)brow * (Hh * Ll) + cp * Ll + l]       = h2x;
                out[(size_t)brow * (Hh * Ll) + (cp + 1) * Ll + l] = h2y;
                mup[r] += h2x * wmu_s[cp] + h2y * wmu_s[cp + 1];
            }
        }
    }
    // reduce mu over the 16 column-threads (lanes 0..15 / 16..31 per warp)
#pragma unroll
    for (int r = 0; r < 4; ++r) {
#pragma unroll
        for (int o = 8; o >= 1; o >>= 1)
            mup[r] += __shfl_down_sync(0xffffffffu, mup[r], o, 16);
    }
    if (tc == 0) {
        float lvv = fmaxf(log_var[l], -3.0f);
        float bm  = bmu[l];
#pragma unroll
        for (int r = 0; r < 4; ++r) {
            int brow = b0 + tr4 + r;
            out[BHL + brow * Ll + l]      = mup[r] + bm;
            out[BHL + BL + brow * Ll + l] = lvv;
        }
    }
}

extern "C" void kernel_launch(void* const* d_in, const int* in_sizes, int n_in,
                              void* d_out, int out_size) {
    const float* hidden  = (const float*)d_in[0];
    const float* x       = (const float*)d_in[1];
    const float* mask    = (const float*)d_in[2];
    const float* Wir     = (const float*)d_in[3];
    const float* bir     = (const float*)d_in[4];
    const float* Wiz     = (const float*)d_in[5];
    const float* biz     = (const float*)d_in[6];
    const float* Win     = (const float*)d_in[7];
    const float* bin_    = (const float*)d_in[8];
    const float* Whr     = (const float*)d_in[9];
    const float* Whz     = (const float*)d_in[10];
    const float* Whn     = (const float*)d_in[11];
    const float* bhn     = (const float*)d_in[12];
    const float* W1      = (const float*)d_in[13];
    const float* b1      = (const float*)d_in[14];
    const float* W2      = (const float*)d_in[15];
    const float* b2      = (const float*)d_in[16];
    const float* Wmu     = (const float*)d_in[17];
    const float* bmu     = (const float*)d_in[18];
    const float* log_var = (const float*)d_in[19];
    float* out = (float*)d_out;

    cudaFuncSetAttribute(prnn_kernel,
                         cudaFuncAttributeMaxDynamicSharedMemorySize, SMEM_BYTES);

    dim3 grid(Ll * (Bb / BT));   // 4096 blocks, l fastest -> L2 weight reuse
    dim3 block(NT);
    prnn_kernel<<<grid, block, SMEM_BYTES>>>(
        hidden, x, mask, Wir, bir, Wiz, biz, Win, bin_,
        Whr, Whz, Whn, bhn, W1, b1, W2, b2, Wmu, bmu, log_var, out);
}